// round 11
// baseline (speedup 1.0000x reference)
#include <cuda_runtime.h>
#include <cstdint>

#define DEVINL __device__ __forceinline__

constexpr int B = 4, N = 4096, K = 10, BN = B * N;
constexpr int NSPLIT = 8, ZLEN = N / NSPLIT;
constexpr int KNNBLK = 64 * B * NSPLIT;     // 2048 kNN blocks per layer
constexpr float SLOPE = 0.2f;
constexpr float BNS = 0.9999950000374997f;  // 1/sqrt(1+1e-5)
constexpr float NEG_INF = -3.4e38f;

DEVINL void fma2(unsigned long long& acc, unsigned long long a, unsigned long long b) {
    asm("fma.rn.f32x2 %0, %1, %2, %0;" : "+l"(acc) : "l"(a), "l"(b));
}
DEVINL float f2sum(unsigned long long v) {
    float2 f = *reinterpret_cast<float2*>(&v);
    return f.x + f.y;
}
struct U64x2 { unsigned long long a, b; };
DEVINL U64x2 asu64x2(const float4& v) {
    U64x2 r;
    r.a = *reinterpret_cast<const unsigned long long*>(&v.x);
    r.b = *reinterpret_cast<const unsigned long long*>(&v.z);
    return r;
}

// ---------------- scratch ----------------
__device__ float g_cat[BN * 512];
__device__ float g_AC[BN * 512];
__device__ float g_sq[BN];
__device__ int   g_knn[BN * K];
__device__ float g_pkv[(size_t)BN * NSPLIT * K];
__device__ int   g_pki[(size_t)BN * NSPLIT * K];
__device__ float g_part[256 * 1024];
__device__ float g_h0[B * 1024];
__device__ float g_y1[B * 512];
__device__ float g_y2[B * 256];

// ---------------- partial-list merge: NSPLIT sorted K-lists per query ------
__global__ void knnmerge_kernel() {
    int q = blockIdx.x * blockDim.x + threadIdx.x;
    if (q >= BN) return;
    const float* pv = g_pkv + (size_t)q * NSPLIT * K;
    const int*   pi = g_pki + (size_t)q * NSPLIT * K;
    int h[NSPLIT];
#pragma unroll
    for (int s = 0; s < NSPLIT; ++s) h[s] = 0;
    int* out = g_knn + (size_t)q * K;
#pragma unroll
    for (int j = 0; j < K; ++j) {
        float bv = NEG_INF; int bi = 0x7fffffff; int bs = 0;
#pragma unroll
        for (int s = 0; s < NSPLIT; ++s) {
            if (h[s] < K) {
                float v = pv[s * K + h[s]];
                int   i = pi[s * K + h[s]];
                if (v > bv || (v == bv && i < bi)) { bv = v; bi = i; bs = s; }
            }
        }
        h[bs]++;
        out[j] = bi;
    }
}

// ================= knn device bodies =================
// layer-1 kNN (D=3), candidate-split; uses dynamic smem buffer
DEVINL void knn1_body(const float* __restrict__ x, int blk, char* smem) {
    constexpr int CR4 = 32;
    float4* Q4 = (float4*)smem;
    float4* C4 = (float4*)(smem + 64 * 16);
    float*  Ss = (float*)(smem + 64 * 16 + 2 * CR4 * 16);
    float*  Mv = (float*)smem;
    int*    Mi = (int*)(smem + 64 * 4 * K * 4);

    int tid = threadIdx.x;
    int tx = tid & 15, ty = tid >> 4;
    int rq = tid & 63, rs = tid >> 6;
    int qbase = (blk & 63) * 64;
    int b = (blk >> 6) & 3;
    int z = blk >> 8;
    int cb0 = z * ZLEN;
    const float* xb = x + (size_t)b * N * 3;
    int qglob = qbase + rq;

    float lv[K]; int li[K];
#pragma unroll
    for (int j = 0; j < K; ++j) { lv[j] = NEG_INF; li[j] = 0x7fffffff; }

    for (int i = tid; i < 64; i += 256) {
        const float* p = xb + (size_t)(qbase + i) * 3;
        Q4[i] = make_float4(p[0], p[1], p[2], 0.f);
    }

    float4 creg;
    auto load_c = [&](int cb) {
        if (tid < 32) {
            const float* p = xb + (size_t)(cb + tid) * 3;
            creg = make_float4(p[0], p[1], p[2], 0.f);
        }
    };
    load_c(cb0);

    for (int cb = cb0; cb < cb0 + ZLEN; cb += 32) {
        int buf = ((cb - cb0) >> 5) & 1;
        if (tid < 32) C4[buf * CR4 + tid] = creg;
        if (cb + 32 < cb0 + ZLEN) load_c(cb + 32);
        __syncthreads();

        const float4* Cb = C4 + buf * CR4;
        U64x2 qv[4], cv[2];
#pragma unroll
        for (int qi = 0; qi < 4; ++qi) qv[qi] = asu64x2(Q4[ty + 16 * qi]);
#pragma unroll
        for (int ci = 0; ci < 2; ++ci) cv[ci] = asu64x2(Cb[tx + 16 * ci]);

        float sc[2];
#pragma unroll
        for (int ci = 0; ci < 2; ++ci) {
            unsigned long long a = 0ull;
            fma2(a, cv[ci].a, cv[ci].a);
            fma2(a, cv[ci].b, cv[ci].b);
            sc[ci] = f2sum(a);
        }

        unsigned long long acc2[4][2];
#pragma unroll
        for (int qi = 0; qi < 4; ++qi) { acc2[qi][0] = 0ull; acc2[qi][1] = 0ull; }
#pragma unroll
        for (int qi = 0; qi < 4; ++qi)
#pragma unroll
            for (int ci = 0; ci < 2; ++ci) {
                fma2(acc2[qi][ci], qv[qi].a, cv[ci].a);
                fma2(acc2[qi][ci], qv[qi].b, cv[ci].b);
            }
#pragma unroll
        for (int qi = 0; qi < 4; ++qi) {
            Ss[(ty + 16 * qi) * 33 + tx]      = 2.f * f2sum(acc2[qi][0]) - sc[0];
            Ss[(ty + 16 * qi) * 33 + tx + 16] = 2.f * f2sum(acc2[qi][1]) - sc[1];
        }
        __syncthreads();

#pragma unroll
        for (int j = 0; j < 8; ++j) {
            int c = cb + rs * 8 + j;
            float v = Ss[rq * 33 + rs * 8 + j];
            if (c != qglob) {
                if (v > lv[K - 1] || (v == lv[K - 1] && c < li[K - 1])) {
                    float cvv = v; int cid = c;
#pragma unroll
                    for (int t = 0; t < K; ++t) {
                        bool better = (cvv > lv[t]) || (cvv == lv[t] && cid < li[t]);
                        float tv = lv[t]; int ti = li[t];
                        if (better) { lv[t] = cvv; li[t] = cid; cvv = tv; cid = ti; }
                    }
                }
            }
        }
        __syncthreads();
    }
    __syncthreads();

#pragma unroll
    for (int j = 0; j < K; ++j) {
        Mv[(rq * 4 + rs) * K + j] = lv[j];
        Mi[(rq * 4 + rs) * K + j] = li[j];
    }
    __syncthreads();
    if (tid < 64) {
        int h[4] = {0, 0, 0, 0};
        int base = tid * 4 * K;
        float* pv = g_pkv + ((size_t)(b * N + qbase + tid) * NSPLIT + z) * K;
        int*   pi = g_pki + ((size_t)(b * N + qbase + tid) * NSPLIT + z) * K;
        for (int j = 0; j < K; ++j) {
            float bv = NEG_INF; int bi = 0x7fffffff; int bs = 0;
#pragma unroll
            for (int s = 0; s < 4; ++s) {
                if (h[s] < K) {
                    float v = Mv[base + s * K + h[s]];
                    int   i = Mi[base + s * K + h[s]];
                    if (v > bv || (v == bv && i < bi)) { bv = v; bi = i; bs = s; }
                }
            }
            h[bs]++;
            pv[j] = bv; pi[j] = bi;
        }
    }
}

// kNN body for D in {64,128}: 64q x 32c tile, padded rows, candidate-split
template<int DPAD>
DEVINL void knn_body(int xoff, int blk, char* smem) {
    constexpr int R4  = DPAD / 4;
    constexpr int PAD = R4 + 1;
    constexpr int CR4 = 32 * PAD;
    constexpr int NLD = 32 * R4;
    constexpr int NL  = (NLD + 255) / 256;
    float4* Q4 = (float4*)smem;
    float4* C4 = (float4*)(smem + (size_t)64 * PAD * 16);
    float*  Ss = (float*)(smem + (size_t)64 * PAD * 16 + (size_t)2 * CR4 * 16);
    float*  Mv = (float*)smem;
    int*    Mi = (int*)(smem + 64 * 4 * K * 4);

    const float* x = g_cat + xoff;
    int tid = threadIdx.x;
    int tx = tid & 15, ty = tid >> 4;
    int rq = tid & 63, rs = tid >> 6;
    int qbase = (blk & 63) * 64;
    int b = (blk >> 6) & 3;
    int z = blk >> 8;
    int cb0 = z * ZLEN;
    const float* xb  = x + (size_t)b * N * 512;
    const float* sqb = g_sq + b * N;
    int qglob = qbase + rq;

    float lv[K]; int li[K];
#pragma unroll
    for (int j = 0; j < K; ++j) { lv[j] = NEG_INF; li[j] = 0x7fffffff; }

    for (int i = tid; i < 64 * R4; i += 256) {
        int row = i / R4, dv = i % R4;
        Q4[row * PAD + dv] =
            *(const float4*)(xb + (size_t)(qbase + row) * 512 + dv * 4);
    }

    float4 creg[NL];
    auto load_c = [&](int cb) {
#pragma unroll
        for (int l = 0; l < NL; ++l) {
            int i = tid + l * 256;
            if ((NLD % 256 == 0) || i < NLD) {
                int row = i / R4, dv = i % R4;
                creg[l] = *(const float4*)(xb + (size_t)(cb + row) * 512 + dv * 4);
            }
        }
    };
    auto store_c = [&](int buf) {
#pragma unroll
        for (int l = 0; l < NL; ++l) {
            int i = tid + l * 256;
            if ((NLD % 256 == 0) || i < NLD) {
                int row = i / R4, dv = i % R4;
                C4[buf * CR4 + row * PAD + dv] = creg[l];
            }
        }
    };

    load_c(cb0);

    for (int cb = cb0; cb < cb0 + ZLEN; cb += 32) {
        int buf = ((cb - cb0) >> 5) & 1;
        store_c(buf);
        if (cb + 32 < cb0 + ZLEN) load_c(cb + 32);
        float sc0 = sqb[cb + tx], sc1 = sqb[cb + tx + 16];
        __syncthreads();

        unsigned long long acc2[4][2];
#pragma unroll
        for (int qi = 0; qi < 4; ++qi) { acc2[qi][0] = 0ull; acc2[qi][1] = 0ull; }
        const float4* Cb = C4 + buf * CR4;
        const float4* Qb0 = Q4 + ty * PAD;
        const float4* Cb0 = Cb + tx * PAD;
#pragma unroll
        for (int dv = 0; dv < R4; ++dv) {
            U64x2 qv[4], cv[2];
#pragma unroll
            for (int qi = 0; qi < 4; ++qi)
                qv[qi] = asu64x2(Qb0[16 * qi * PAD + dv]);
#pragma unroll
            for (int ci = 0; ci < 2; ++ci)
                cv[ci] = asu64x2(Cb0[16 * ci * PAD + dv]);
#pragma unroll
            for (int qi = 0; qi < 4; ++qi)
#pragma unroll
                for (int ci = 0; ci < 2; ++ci) {
                    fma2(acc2[qi][ci], qv[qi].a, cv[ci].a);
                    fma2(acc2[qi][ci], qv[qi].b, cv[ci].b);
                }
        }
#pragma unroll
        for (int qi = 0; qi < 4; ++qi) {
            Ss[(ty + 16 * qi) * 33 + tx]      = 2.f * f2sum(acc2[qi][0]) - sc0;
            Ss[(ty + 16 * qi) * 33 + tx + 16] = 2.f * f2sum(acc2[qi][1]) - sc1;
        }
        __syncthreads();

#pragma unroll
        for (int j = 0; j < 8; ++j) {
            int c = cb + rs * 8 + j;
            float v = Ss[rq * 33 + rs * 8 + j];
            if (c != qglob) {
                if (v > lv[K - 1] || (v == lv[K - 1] && c < li[K - 1])) {
                    float cvv = v; int cid = c;
#pragma unroll
                    for (int t = 0; t < K; ++t) {
                        bool better = (cvv > lv[t]) || (cvv == lv[t] && cid < li[t]);
                        float tv = lv[t]; int ti = li[t];
                        if (better) { lv[t] = cvv; li[t] = cid; cvv = tv; cid = ti; }
                    }
                }
            }
        }
    }
    __syncthreads();

#pragma unroll
    for (int j = 0; j < K; ++j) {
        Mv[(rq * 4 + rs) * K + j] = lv[j];
        Mi[(rq * 4 + rs) * K + j] = li[j];
    }
    __syncthreads();
    if (tid < 64) {
        int h[4] = {0, 0, 0, 0};
        int base = tid * 4 * K;
        float* pv = g_pkv + ((size_t)(b * N + qbase + tid) * NSPLIT + z) * K;
        int*   pi = g_pki + ((size_t)(b * N + qbase + tid) * NSPLIT + z) * K;
        for (int j = 0; j < K; ++j) {
            float bv = NEG_INF; int bi = 0x7fffffff; int bs = 0;
#pragma unroll
            for (int s = 0; s < 4; ++s) {
                if (h[s] < K) {
                    float v = Mv[base + s * K + h[s]];
                    int   i = Mi[base + s * K + h[s]];
                    if (v > bv || (v == bv && i < bi)) { bv = v; bi = i; bs = s; }
                }
            }
            h[bs]++;
            pv[j] = bv; pi[j] = bi;
        }
    }
}

// ================= gemm device bodies =================
// layer-1 AC GEMM with inline w1 prep (D=3); uses dynamic smem buffer
DEVINL void gemm1_body(const float* __restrict__ x, const float* __restrict__ w1,
                       int blk, char* smem) {
    float4* Xs = (float4*)smem;
    float4* Ws = Xs + 64;
    int tid = threadIdx.x, tx = tid & 15, ty = tid >> 4;
    int rowbase = (blk & 255) * 64, colbase = (blk >> 8) * 64;

    if (tid < 64) {
        const float* p = x + (size_t)(rowbase + tid) * 3;
        Xs[tid] = make_float4(p[0], p[1], p[2], 0.f);
        int cr = colbase + tid;
        float vv[3];
#pragma unroll
        for (int e = 0; e < 3; ++e) {
            if (cr < 64) vv[e] = w1[cr * 6 + e];
            else { int o = cr - 64; vv[e] = w1[o * 6 + 3 + e] - w1[o * 6 + e]; }
        }
        Ws[tid] = make_float4(vv[0], vv[1], vv[2], 0.f);
    }
    __syncthreads();

    unsigned long long acc2[4][4];
#pragma unroll
    for (int qi = 0; qi < 4; ++qi)
#pragma unroll
        for (int ci = 0; ci < 4; ++ci) acc2[qi][ci] = 0ull;
    U64x2 xv[4], wv[4];
#pragma unroll
    for (int qi = 0; qi < 4; ++qi) xv[qi] = asu64x2(Xs[ty + 16 * qi]);
#pragma unroll
    for (int ci = 0; ci < 4; ++ci) wv[ci] = asu64x2(Ws[tx + 16 * ci]);
#pragma unroll
    for (int qi = 0; qi < 4; ++qi)
#pragma unroll
        for (int ci = 0; ci < 4; ++ci) {
            fma2(acc2[qi][ci], xv[qi].a, wv[ci].a);
            fma2(acc2[qi][ci], xv[qi].b, wv[ci].b);
        }
#pragma unroll
    for (int qi = 0; qi < 4; ++qi)
#pragma unroll
        for (int ci = 0; ci < 4; ++ci)
            g_AC[(size_t)(rowbase + ty + 16 * qi) * 128 + colbase + tx + 16 * ci] =
                f2sum(acc2[qi][ci]);
}

// AC GEMM body with inline weight prep; D in {64,128}, raw w is O x 2D
template<int DG>
DEVINL void gemm_body(int xoff, const float* __restrict__ wraw, int D, int O, int ldo,
                      int blk, char* smem) {
    constexpr int DC  = 32;
    constexpr int RC  = 8;
    constexpr int SWM = 7;
    constexpr int NCH = DG / DC;
    constexpr int TR4 = 64 * RC;   // 512
    constexpr int NL  = 2;
    float4* Xs = (float4*)smem;
    float4* Ws = Xs + 2 * TR4;
    const float* x = g_cat + xoff;
    int tid = threadIdx.x, tx = tid & 15, ty = tid >> 4;
    int rowbase = (blk & 255) * 64, colbase = (blk >> 8) * 64;
    int twoD = 2 * D;
    unsigned long long acc2[4][4];
#pragma unroll
    for (int qi = 0; qi < 4; ++qi)
#pragma unroll
        for (int ci = 0; ci < 4; ++ci) acc2[qi][ci] = 0ull;

    float4 xreg[NL], wreg[NL];
    auto load_xw = [&](int ch) {
        int d0 = ch * DC;
#pragma unroll
        for (int l = 0; l < NL; ++l) {
            int i = tid + l * 256;
            int r = i / RC, dv = i % RC;
            xreg[l] = *(const float4*)(x + (size_t)(rowbase + r) * 512 + d0 + 4 * dv);
            int cr = colbase + r;
            if (cr < O) {
                wreg[l] = *(const float4*)(wraw + (size_t)cr * twoD + d0 + 4 * dv);
            } else {
                int o = cr - O;
                float4 a = *(const float4*)(wraw + (size_t)o * twoD + D + d0 + 4 * dv);
                float4 bq = *(const float4*)(wraw + (size_t)o * twoD + d0 + 4 * dv);
                wreg[l] = make_float4(a.x - bq.x, a.y - bq.y, a.z - bq.z, a.w - bq.w);
            }
        }
    };
    auto store_xw = [&](int buf) {
#pragma unroll
        for (int l = 0; l < NL; ++l) {
            int i = tid + l * 256;
            int r = i / RC, dv = i % RC;
            Xs[buf * TR4 + r * RC + (dv ^ (r & SWM))] = xreg[l];
            Ws[buf * TR4 + r * RC + (dv ^ (r & SWM))] = wreg[l];
        }
    };

    load_xw(0);
    for (int ch = 0; ch < NCH; ++ch) {
        int buf = ch & 1;
        store_xw(buf);
        if (ch + 1 < NCH) load_xw(ch + 1);
        __syncthreads();
        const float4* Xb = Xs + buf * TR4;
        const float4* Wb = Ws + buf * TR4;
#pragma unroll
        for (int dv = 0; dv < RC; ++dv) {
            U64x2 xv[4], wv[4];
#pragma unroll
            for (int qi = 0; qi < 4; ++qi)
                xv[qi] = asu64x2(Xb[(ty + 16 * qi) * RC + (dv ^ (ty & SWM))]);
#pragma unroll
            for (int ci = 0; ci < 4; ++ci)
                wv[ci] = asu64x2(Wb[(tx + 16 * ci) * RC + (dv ^ (tx & SWM))]);
#pragma unroll
            for (int qi = 0; qi < 4; ++qi)
#pragma unroll
                for (int ci = 0; ci < 4; ++ci) {
                    fma2(acc2[qi][ci], xv[qi].a, wv[ci].a);
                    fma2(acc2[qi][ci], xv[qi].b, wv[ci].b);
                }
        }
        __syncthreads();
    }
#pragma unroll
    for (int qi = 0; qi < 4; ++qi)
#pragma unroll
        for (int ci = 0; ci < 4; ++ci)
            g_AC[(size_t)(rowbase + ty + 16 * qi) * ldo + colbase + tx + 16 * ci] =
                f2sum(acc2[qi][ci]);
}

// ================= mega kernels: knn blocks + gemm blocks in one launch =====
__global__ void __launch_bounds__(256) mega1_kernel(const float* __restrict__ points,
                                                    const float* __restrict__ w1) {
    extern __shared__ __align__(16) char dsm[];
    int i = blockIdx.x;
    if (i < KNNBLK) knn1_body(points, i, dsm);
    else            gemm1_body(points, w1, i - KNNBLK, dsm);
}

template<int DK>
__global__ void __launch_bounds__(256) mega_kernel(int xoffK, int xoffG,
                                                   const float* __restrict__ wraw,
                                                   int D, int O, int ldo) {
    extern __shared__ __align__(16) char dsm[];
    int i = blockIdx.x;
    if (i < KNNBLK) knn_body<DK>(xoffK, i, dsm);
    else            gemm_body<DK>(xoffG, wraw, D, O, ldo, i - KNNBLK, dsm);
}

// ================= w5 GEMM: 64x64 tiles + bn/lrelu/row-max epilogue =========
__global__ void __launch_bounds__(256) gemm5_kernel(const float* __restrict__ w5,
                                                    const float* __restrict__ gg,
                                                    const float* __restrict__ bb) {
    constexpr int RC = 8, SWM = 7, NCH = 16, TR4 = 512, NL = 2;
    __shared__ float4 Xs[2 * TR4];
    __shared__ float4 Ws[2 * TR4];
    const float* x = g_cat;
    int tid = threadIdx.x, tx = tid & 15, ty = tid >> 4;
    int rowbase = blockIdx.x * 64, colbase = blockIdx.y * 64;
    unsigned long long acc2[4][4];
#pragma unroll
    for (int qi = 0; qi < 4; ++qi)
#pragma unroll
        for (int ci = 0; ci < 4; ++ci) acc2[qi][ci] = 0ull;

    float4 xreg[NL], wreg[NL];
    auto load_xw = [&](int ch) {
        int d0 = ch * 32;
#pragma unroll
        for (int l = 0; l < NL; ++l) {
            int i = tid + l * 256;
            int r = i / RC, dv = i % RC;
            xreg[l] = *(const float4*)(x + (size_t)(rowbase + r) * 512 + d0 + 4 * dv);
            wreg[l] = *(const float4*)(w5 + (size_t)(colbase + r) * 512 + d0 + 4 * dv);
        }
    };
    auto store_xw = [&](int buf) {
#pragma unroll
        for (int l = 0; l < NL; ++l) {
            int i = tid + l * 256;
            int r = i / RC, dv = i % RC;
            Xs[buf * TR4 + r * RC + (dv ^ (r & SWM))] = xreg[l];
            Ws[buf * TR4 + r * RC + (dv ^ (r & SWM))] = wreg[l];
        }
    };

    load_xw(0);
    for (int ch = 0; ch < NCH; ++ch) {
        int buf = ch & 1;
        store_xw(buf);
        if (ch + 1 < NCH) load_xw(ch + 1);
        __syncthreads();
        const float4* Xb = Xs + buf * TR4;
        const float4* Wb = Ws + buf * TR4;
#pragma unroll
        for (int dv = 0; dv < RC; ++dv) {
            U64x2 xv[4], wv[4];
#pragma unroll
            for (int qi = 0; qi < 4; ++qi)
                xv[qi] = asu64x2(Xb[(ty + 16 * qi) * RC + (dv ^ (ty & SWM))]);
#pragma unroll
            for (int ci = 0; ci < 4; ++ci)
                wv[ci] = asu64x2(Wb[(tx + 16 * ci) * RC + (dv ^ (tx & SWM))]);
#pragma unroll
            for (int qi = 0; qi < 4; ++qi)
#pragma unroll
                for (int ci = 0; ci < 4; ++ci) {
                    fma2(acc2[qi][ci], xv[qi].a, wv[ci].a);
                    fma2(acc2[qi][ci], xv[qi].b, wv[ci].b);
                }
        }
        __syncthreads();
    }

    float cm[4];
#pragma unroll
    for (int ci = 0; ci < 4; ++ci) {
        int col = colbase + tx + 16 * ci;
        float g = BNS * gg[col], be = bb[col];
        float m = NEG_INF;
#pragma unroll
        for (int qi = 0; qi < 4; ++qi) {
            float v = g * f2sum(acc2[qi][ci]) + be;
            v = (v > 0.f) ? v : SLOPE * v;
            m = fmaxf(m, v);
        }
        cm[ci] = m;
    }
    float* R = (float*)Xs;
#pragma unroll
    for (int ci = 0; ci < 4; ++ci) R[ty * 64 + tx + 16 * ci] = cm[ci];
    __syncthreads();
    if (tid < 64) {
        float m = R[tid];
#pragma unroll
        for (int t = 1; t < 16; ++t) m = fmaxf(m, R[t * 64 + tid]);
        g_part[(size_t)blockIdx.x * 1024 + colbase + tid] = m;
    }
}

// ---------------- gather + bn + lrelu + max, fused next-layer sqnorm -------
__global__ void edgemax_kernel(const float* __restrict__ gamma, const float* __restrict__ beta,
                               int O, int catoff) {
    int n = blockIdx.x;
    int o = threadIdx.x;
    int b = n >> 12;
    __shared__ int sidx[K];
    __shared__ float ps[8];
    if (o < K) sidx[o] = g_knn[(size_t)n * K + o];
    __syncthreads();
    int twoO = 2 * O;
    float cterm = g_AC[(size_t)n * twoO + O + o];
    float g = BNS * gamma[o], be = beta[o];
    int base = b << 12;
    float m = NEG_INF;
#pragma unroll
    for (int j = 0; j < K; ++j) {
        float a = g_AC[(size_t)(base + sidx[j]) * twoO + o];
        float v = g * (a + cterm) + be;
        v = (v > 0.f) ? v : SLOPE * v;
        m = fmaxf(m, v);
    }
    g_cat[(size_t)n * 512 + catoff + o] = m;

    float p = m * m;
#pragma unroll
    for (int off = 16; off; off >>= 1) p += __shfl_down_sync(0xffffffffu, p, off);
    if ((o & 31) == 0) ps[o >> 5] = p;
    __syncthreads();
    if (o == 0) {
        float s = 0.f;
        int nw = O >> 5;
        for (int w = 0; w < nw; ++w) s += ps[w];
        g_sq[n] = s;
    }
}

// ---------------- final max reduce + warp-per-output MLP head -------------
__global__ void maxreduce_kernel() {
    int i = blockIdx.x * blockDim.x + threadIdx.x;
    if (i >= B * 1024) return;
    int b = i / 1024, o = i % 1024;
    float m = NEG_INF;
    for (int j = 0; j < 64; ++j)
        m = fmaxf(m, g_part[(size_t)(b * 64 + j) * 1024 + o]);
    g_h0[i] = m;
}

__global__ void fc1_kernel(const float* __restrict__ fw1, const float* __restrict__ fg1,
                           const float* __restrict__ fbt1) {
    int gw = (blockIdx.x * blockDim.x + threadIdx.x) >> 5;
    int lane = threadIdx.x & 31;
    if (gw >= B * 512) return;
    int b = gw >> 9, o = gw & 511;
    const float* h = g_h0 + b * 1024;
    const float* wr = fw1 + (size_t)o * 1024;
    float s = 0.f;
    for (int c = lane; c < 1024; c += 32) s += h[c] * wr[c];
#pragma unroll
    for (int off = 16; off; off >>= 1) s += __shfl_down_sync(0xffffffffu, s, off);
    if (lane == 0) {
        float v = BNS * fg1[o] * s + fbt1[o];
        g_y1[gw] = (v > 0.f) ? v : SLOPE * v;
    }
}

__global__ void fc2_kernel(const float* __restrict__ fw2, const float* __restrict__ fb2,
                           const float* __restrict__ fg2, const float* __restrict__ fbt2) {
    int gw = (blockIdx.x * blockDim.x + threadIdx.x) >> 5;
    int lane = threadIdx.x & 31;
    if (gw >= B * 256) return;
    int b = gw >> 8, o = gw & 255;
    const float* h = g_y1 + b * 512;
    const float* wr = fw2 + (size_t)o * 512;
    float s = 0.f;
    for (int c = lane; c < 512; c += 32) s += h[c] * wr[c];
#pragma unroll
    for (int off = 16; off; off >>= 1) s += __shfl_down_sync(0xffffffffu, s, off);
    if (lane == 0) {
        float v = BNS * fg2[o] * (s + fb2[o]) + fbt2[o];
        g_y2[gw] = (v > 0.f) ? v : SLOPE * v;
    }
}

__global__ void fc3_kernel(const float* __restrict__ fw3, const float* __restrict__ fb3,
                           float* __restrict__ out) {
    int gw = threadIdx.x >> 5;
    int lane = threadIdx.x & 31;
    if (gw >= B * 3) return;
    int b = gw / 3, o = gw % 3;
    const float* h = g_y2 + b * 256;
    const float* wr = fw3 + (size_t)o * 256;
    float s = 0.f;
    for (int c = lane; c < 256; c += 32) s += h[c] * wr[c];
#pragma unroll
    for (int off = 16; off; off >>= 1) s += __shfl_down_sync(0xffffffffu, s, off);
    if (lane == 0) out[gw] = s + fb3[o];
}

// ---------------- launch ----------------
static int knn_smem_bytes(int R4) {
    int pad = R4 + 1;
    int s = 64 * pad * 16 + 2 * 32 * pad * 16 + 64 * 33 * 4;
    int merge = 64 * 4 * K * 8;
    int gemm = 2 * 512 * 16 * 2;   // gemm body: Xs+Ws double-buffered
    int m = s > merge ? s : merge;
    return m > gemm ? m : gemm;
}

extern "C" void kernel_launch(void* const* d_in, const int* in_sizes, int n_in,
                              void* d_out, int out_size) {
    const float* points = (const float*)d_in[0];
    const float* w1 = (const float*)d_in[2];
    const float* g1 = (const float*)d_in[3];
    const float* b1 = (const float*)d_in[4];
    const float* w2 = (const float*)d_in[5];
    const float* g2 = (const float*)d_in[6];
    const float* b2 = (const float*)d_in[7];
    const float* w3 = (const float*)d_in[8];
    const float* g3 = (const float*)d_in[9];
    const float* b3 = (const float*)d_in[10];
    const float* w4 = (const float*)d_in[11];
    const float* g4 = (const float*)d_in[12];
    const float* b4 = (const float*)d_in[13];
    const float* w5 = (const float*)d_in[14];
    const float* g5 = (const float*)d_in[15];
    const float* b5 = (const float*)d_in[16];
    const float* fw1 = (const float*)d_in[17];
    const float* fg1 = (const float*)d_in[18];
    const float* fbt1 = (const float*)d_in[19];
    const float* fw2 = (const float*)d_in[20];
    const float* fb2 = (const float*)d_in[21];
    const float* fg2 = (const float*)d_in[22];
    const float* fbt2 = (const float*)d_in[23];
    const float* fw3 = (const float*)d_in[24];
    const float* fb3 = (const float*)d_in[25];
    float* out = (float*)d_out;

    int sm1 = 64 * 16 + 2 * 32 * 16 + 64 * 33 * 4;   // knn1 region
    int merge1 = 64 * 4 * K * 8;
    if (merge1 > sm1) sm1 = merge1;                  // 20480; gemm1 needs 2KB only
    int sm64  = knn_smem_bytes(16);
    int sm128 = knn_smem_bytes(32);
    static bool attr_done = false;
    if (!attr_done) {
        cudaFuncSetAttribute(mega1_kernel,     cudaFuncAttributeMaxDynamicSharedMemorySize, sm1);
        cudaFuncSetAttribute(mega_kernel<64>,  cudaFuncAttributeMaxDynamicSharedMemorySize, sm64);
        cudaFuncSetAttribute(mega_kernel<128>, cudaFuncAttributeMaxDynamicSharedMemorySize, sm128);
        attr_done = true;
    }

    int mergegrid = (BN + 255) / 256;

    // ---- EdgeConv 1 (D=3, O=64): kNN + AC-GEMM overlapped in one launch
    mega1_kernel<<<KNNBLK + 512, 256, sm1>>>(points, w1);             // idx 0
    knnmerge_kernel<<<mergegrid, 256>>>();                            // idx 1
    edgemax_kernel<<<BN, 64>>>(g1, b1, 64, 0);                        // idx 2

    // ---- EdgeConv 2 (D=64, O=64) -> cat cols [64,128)
    mega_kernel<64><<<KNNBLK + 512, 256, sm64>>>(0, 0, w2, 64, 64, 128);   // idx 3 (profiled)
    knnmerge_kernel<<<mergegrid, 256>>>();
    edgemax_kernel<<<BN, 64>>>(g2, b2, 64, 64);

    // ---- EdgeConv 3 (D=64, O=128) -> cat cols [128,256)
    mega_kernel<64><<<KNNBLK + 1024, 256, sm64>>>(64, 64, w3, 64, 128, 256);
    knnmerge_kernel<<<mergegrid, 256>>>();
    edgemax_kernel<<<BN, 128>>>(g3, b3, 128, 128);

    // ---- EdgeConv 4 (D=128, O=256) -> cat cols [256,512)
    mega_kernel<128><<<KNNBLK + 2048, 256, sm128>>>(128, 128, w4, 128, 256, 512);
    knnmerge_kernel<<<mergegrid, 256>>>();
    edgemax_kernel<<<BN, 256>>>(g4, b4, 256, 256);

    // ---- w5 GEMM + bn + lrelu + row-block max
    gemm5_kernel<<<dim3(BN / 64, 16), 256>>>(w5, g5, b5);
    maxreduce_kernel<<<(B * 1024 + 255) / 256, 256>>>();

    // ---- MLP head
    fc1_kernel<<<(B * 512 * 32 + 255) / 256, 256>>>(fw1, fg1, fbt1);
    fc2_kernel<<<(B * 256 * 32 + 255) / 256, 256>>>(fw2, fb2, fg2, fbt2);
    fc3_kernel<<<1, 384>>>(fw3, fb3, out);
}

// round 12
// speedup vs baseline: 1.8114x; 1.8114x over previous
#include <cuda_runtime.h>
#include <cstdint>

#define DEVINL __device__ __forceinline__

constexpr int B = 4, N = 4096, K = 10, BN = B * N;
constexpr int NSPLIT = 8, ZLEN = N / NSPLIT;
constexpr float SLOPE = 0.2f;
constexpr float BNS = 0.9999950000374997f; // 1/sqrt(1+1e-5)
constexpr float NEG_INF = -3.4e38f;

DEVINL void fma2(unsigned long long& acc, unsigned long long a, unsigned long long b) {
    asm("fma.rn.f32x2 %0, %1, %2, %0;" : "+l"(acc) : "l"(a), "l"(b));
}
DEVINL float f2sum(unsigned long long v) {
    float2 f = *reinterpret_cast<float2*>(&v);
    return f.x + f.y;
}
struct U64x2 { unsigned long long a, b; };
DEVINL U64x2 asu64x2(const float4& v) {
    U64x2 r;
    r.a = *reinterpret_cast<const unsigned long long*>(&v.x);
    r.b = *reinterpret_cast<const unsigned long long*>(&v.z);
    return r;
}

// ---------------- scratch ----------------
__device__ float g_cat[BN * 512];
__device__ float g_AC[BN * 512];
__device__ float g_sq[BN];
__device__ int   g_knn[BN * K];
__device__ float g_pkv[(size_t)BN * NSPLIT * K];
__device__ int   g_pki[(size_t)BN * NSPLIT * K];
__device__ float g_wc[512 * 128];
__device__ float g_part[256 * 1024];
__device__ float g_h0[B * 1024];
__device__ float g_y1[B * 512];
__device__ float g_y2[B * 256];

// ---------------- partial-list merge: NSPLIT sorted K-lists per query ------
__global__ void knnmerge_kernel() {
    int q = blockIdx.x * blockDim.x + threadIdx.x;
    if (q >= BN) return;
    const float* pv = g_pkv + (size_t)q * NSPLIT * K;
    const int*   pi = g_pki + (size_t)q * NSPLIT * K;
    int h[NSPLIT];
#pragma unroll
    for (int s = 0; s < NSPLIT; ++s) h[s] = 0;
    int* out = g_knn + (size_t)q * K;
#pragma unroll
    for (int j = 0; j < K; ++j) {
        float bv = NEG_INF; int bi = 0x7fffffff; int bs = 0;
#pragma unroll
        for (int s = 0; s < NSPLIT; ++s) {
            if (h[s] < K) {
                float v = pv[s * K + h[s]];
                int   i = pi[s * K + h[s]];
                if (v > bv || (v == bv && i < bi)) { bv = v; bi = i; bs = s; }
            }
        }
        h[bs]++;
        out[j] = bi;
    }
}

// ================= layer-1 kNN (D=3), candidate-split =================
__global__ void __launch_bounds__(256) knn1_kernel(const float* __restrict__ x) {
    constexpr int CR4 = 32;
    extern __shared__ __align__(16) char smem[];
    float4* Q4 = (float4*)smem;
    float4* C4 = (float4*)(smem + 64 * 16);
    float*  Ss = (float*)(smem + 64 * 16 + 2 * CR4 * 16);
    float*  Mv = (float*)smem;
    int*    Mi = (int*)(smem + 64 * 4 * K * 4);

    int tid = threadIdx.x;
    int tx = tid & 15, ty = tid >> 4;
    int rq = tid & 63, rs = tid >> 6;
    int b = blockIdx.y, qbase = blockIdx.x * 64;
    int cb0 = blockIdx.z * ZLEN;
    const float* xb = x + (size_t)b * N * 3;
    int qglob = qbase + rq;

    float lv[K]; int li[K];
#pragma unroll
    for (int j = 0; j < K; ++j) { lv[j] = NEG_INF; li[j] = 0x7fffffff; }

    for (int i = tid; i < 64; i += 256) {
        const float* p = xb + (size_t)(qbase + i) * 3;
        Q4[i] = make_float4(p[0], p[1], p[2], 0.f);
    }

    float4 creg;
    auto load_c = [&](int cb) {
        if (tid < 32) {
            const float* p = xb + (size_t)(cb + tid) * 3;
            creg = make_float4(p[0], p[1], p[2], 0.f);
        }
    };
    load_c(cb0);

    for (int cb = cb0; cb < cb0 + ZLEN; cb += 32) {
        int buf = ((cb - cb0) >> 5) & 1;
        if (tid < 32) C4[buf * CR4 + tid] = creg;
        if (cb + 32 < cb0 + ZLEN) load_c(cb + 32);
        __syncthreads();

        const float4* Cb = C4 + buf * CR4;
        U64x2 qv[4], cv[2];
#pragma unroll
        for (int qi = 0; qi < 4; ++qi) qv[qi] = asu64x2(Q4[ty + 16 * qi]);
#pragma unroll
        for (int ci = 0; ci < 2; ++ci) cv[ci] = asu64x2(Cb[tx + 16 * ci]);

        float sc[2];
#pragma unroll
        for (int ci = 0; ci < 2; ++ci) {
            unsigned long long a = 0ull;
            fma2(a, cv[ci].a, cv[ci].a);
            fma2(a, cv[ci].b, cv[ci].b);
            sc[ci] = f2sum(a);
        }

        unsigned long long acc2[4][2];
#pragma unroll
        for (int qi = 0; qi < 4; ++qi) { acc2[qi][0] = 0ull; acc2[qi][1] = 0ull; }
#pragma unroll
        for (int qi = 0; qi < 4; ++qi)
#pragma unroll
            for (int ci = 0; ci < 2; ++ci) {
                fma2(acc2[qi][ci], qv[qi].a, cv[ci].a);
                fma2(acc2[qi][ci], qv[qi].b, cv[ci].b);
            }
#pragma unroll
        for (int qi = 0; qi < 4; ++qi) {
            Ss[(ty + 16 * qi) * 33 + tx]      = 2.f * f2sum(acc2[qi][0]) - sc[0];
            Ss[(ty + 16 * qi) * 33 + tx + 16] = 2.f * f2sum(acc2[qi][1]) - sc[1];
        }
        __syncthreads();

#pragma unroll
        for (int j = 0; j < 8; ++j) {
            int c = cb + rs * 8 + j;
            float v = Ss[rq * 33 + rs * 8 + j];
            if (c != qglob) {
                if (v > lv[K - 1] || (v == lv[K - 1] && c < li[K - 1])) {
                    float cvv = v; int cid = c;
#pragma unroll
                    for (int t = 0; t < K; ++t) {
                        bool better = (cvv > lv[t]) || (cvv == lv[t] && cid < li[t]);
                        float tv = lv[t]; int ti = li[t];
                        if (better) { lv[t] = cvv; li[t] = cid; cvv = tv; cid = ti; }
                    }
                }
            }
        }
        __syncthreads();
    }
    __syncthreads();

#pragma unroll
    for (int j = 0; j < K; ++j) {
        Mv[(rq * 4 + rs) * K + j] = lv[j];
        Mi[(rq * 4 + rs) * K + j] = li[j];
    }
    __syncthreads();
    if (tid < 64) {
        int h[4] = {0, 0, 0, 0};
        int base = tid * 4 * K;
        float* pv = g_pkv + ((size_t)(b * N + qbase + tid) * NSPLIT + blockIdx.z) * K;
        int*   pi = g_pki + ((size_t)(b * N + qbase + tid) * NSPLIT + blockIdx.z) * K;
        for (int j = 0; j < K; ++j) {
            float bv = NEG_INF; int bi = 0x7fffffff; int bs = 0;
#pragma unroll
            for (int s = 0; s < 4; ++s) {
                if (h[s] < K) {
                    float v = Mv[base + s * K + h[s]];
                    int   i = Mi[base + s * K + h[s]];
                    if (v > bv || (v == bv && i < bi)) { bv = v; bi = i; bs = s; }
                }
            }
            h[bs]++;
            pv[j] = bv; pi[j] = bi;
        }
    }
}

// ====== kNN for D in {64,128}: 64q x 32c tile, padded rows, occ-forced ======
template<int DPAD, int MINB>
__global__ void __launch_bounds__(256, MINB) knn_kernel(int xoff) {
    constexpr int R4  = DPAD / 4;
    constexpr int PAD = R4 + 1;               // odd stride -> conflict-free, affine
    constexpr int CR4 = 32 * PAD;
    constexpr int NLD = 32 * R4;
    constexpr int NL  = (NLD + 255) / 256;
    extern __shared__ __align__(16) char smem[];
    float4* Q4 = (float4*)smem;
    float4* C4 = (float4*)(smem + (size_t)64 * PAD * 16);
    float*  Ss = (float*)(smem + (size_t)64 * PAD * 16 + (size_t)2 * CR4 * 16);
    float*  Mv = (float*)smem;
    int*    Mi = (int*)(smem + 64 * 4 * K * 4);

    const float* x = g_cat + xoff;
    int tid = threadIdx.x;
    int tx = tid & 15, ty = tid >> 4;
    int rq = tid & 63, rs = tid >> 6;
    int b = blockIdx.y, qbase = blockIdx.x * 64;
    int cb0 = blockIdx.z * ZLEN;
    const float* xb  = x + (size_t)b * N * 512;
    const float* sqb = g_sq + b * N;
    int qglob = qbase + rq;

    float lv[K]; int li[K];
#pragma unroll
    for (int j = 0; j < K; ++j) { lv[j] = NEG_INF; li[j] = 0x7fffffff; }

    for (int i = tid; i < 64 * R4; i += 256) {
        int row = i / R4, dv = i % R4;
        Q4[row * PAD + dv] =
            *(const float4*)(xb + (size_t)(qbase + row) * 512 + dv * 4);
    }

    float4 creg[NL];
    auto load_c = [&](int cb) {
#pragma unroll
        for (int l = 0; l < NL; ++l) {
            int i = tid + l * 256;
            if ((NLD % 256 == 0) || i < NLD) {
                int row = i / R4, dv = i % R4;
                creg[l] = *(const float4*)(xb + (size_t)(cb + row) * 512 + dv * 4);
            }
        }
    };
    auto store_c = [&](int buf) {
#pragma unroll
        for (int l = 0; l < NL; ++l) {
            int i = tid + l * 256;
            if ((NLD % 256 == 0) || i < NLD) {
                int row = i / R4, dv = i % R4;
                C4[buf * CR4 + row * PAD + dv] = creg[l];
            }
        }
    };

    load_c(cb0);

    for (int cb = cb0; cb < cb0 + ZLEN; cb += 32) {
        int buf = ((cb - cb0) >> 5) & 1;
        store_c(buf);
        if (cb + 32 < cb0 + ZLEN) load_c(cb + 32);
        float sc0 = sqb[cb + tx], sc1 = sqb[cb + tx + 16];
        __syncthreads();

        unsigned long long acc2[4][2];
#pragma unroll
        for (int qi = 0; qi < 4; ++qi) { acc2[qi][0] = 0ull; acc2[qi][1] = 0ull; }
        const float4* Cb = C4 + buf * CR4;
        const float4* Qb0 = Q4 + ty * PAD;
        const float4* Cb0 = Cb + tx * PAD;
#pragma unroll
        for (int dv = 0; dv < R4; ++dv) {
            U64x2 qv[4], cv[2];
#pragma unroll
            for (int qi = 0; qi < 4; ++qi)
                qv[qi] = asu64x2(Qb0[16 * qi * PAD + dv]);
#pragma unroll
            for (int ci = 0; ci < 2; ++ci)
                cv[ci] = asu64x2(Cb0[16 * ci * PAD + dv]);
#pragma unroll
            for (int qi = 0; qi < 4; ++qi)
#pragma unroll
                for (int ci = 0; ci < 2; ++ci) {
                    fma2(acc2[qi][ci], qv[qi].a, cv[ci].a);
                    fma2(acc2[qi][ci], qv[qi].b, cv[ci].b);
                }
        }
#pragma unroll
        for (int qi = 0; qi < 4; ++qi) {
            Ss[(ty + 16 * qi) * 33 + tx]      = 2.f * f2sum(acc2[qi][0]) - sc0;
            Ss[(ty + 16 * qi) * 33 + tx + 16] = 2.f * f2sum(acc2[qi][1]) - sc1;
        }
        __syncthreads();

#pragma unroll
        for (int j = 0; j < 8; ++j) {
            int c = cb + rs * 8 + j;
            float v = Ss[rq * 33 + rs * 8 + j];
            if (c != qglob) {
                if (v > lv[K - 1] || (v == lv[K - 1] && c < li[K - 1])) {
                    float cvv = v; int cid = c;
#pragma unroll
                    for (int t = 0; t < K; ++t) {
                        bool better = (cvv > lv[t]) || (cvv == lv[t] && cid < li[t]);
                        float tv = lv[t]; int ti = li[t];
                        if (better) { lv[t] = cvv; li[t] = cid; cvv = tv; cid = ti; }
                    }
                }
            }
        }
    }
    __syncthreads();

#pragma unroll
    for (int j = 0; j < K; ++j) {
        Mv[(rq * 4 + rs) * K + j] = lv[j];
        Mi[(rq * 4 + rs) * K + j] = li[j];
    }
    __syncthreads();
    if (tid < 64) {
        int h[4] = {0, 0, 0, 0};
        int base = tid * 4 * K;
        float* pv = g_pkv + ((size_t)(b * N + qbase + tid) * NSPLIT + blockIdx.z) * K;
        int*   pi = g_pki + ((size_t)(b * N + qbase + tid) * NSPLIT + blockIdx.z) * K;
        for (int j = 0; j < K; ++j) {
            float bv = NEG_INF; int bi = 0x7fffffff; int bs = 0;
#pragma unroll
            for (int s = 0; s < 4; ++s) {
                if (h[s] < K) {
                    float v = Mv[base + s * K + h[s]];
                    int   i = Mi[base + s * K + h[s]];
                    if (v > bv || (v == bv && i < bi)) { bv = v; bi = i; bs = s; }
                }
            }
            h[bs]++;
            pv[j] = bv; pi[j] = bi;
        }
    }
}

// ---------------- layer-1 AC GEMM with inline w1 prep (D=3) ----------------
__global__ void __launch_bounds__(256) gemm1_kernel(const float* __restrict__ x,
                                                    const float* __restrict__ w1) {
    __shared__ float4 Xs[64];
    __shared__ float4 Ws[64];
    int tid = threadIdx.x, tx = tid & 15, ty = tid >> 4;
    int rowbase = blockIdx.x * 64, colbase = blockIdx.y * 64;

    if (tid < 64) {
        const float* p = x + (size_t)(rowbase + tid) * 3;
        Xs[tid] = make_float4(p[0], p[1], p[2], 0.f);
        int cr = colbase + tid;
        float vv[3];
#pragma unroll
        for (int e = 0; e < 3; ++e) {
            if (cr < 64) vv[e] = w1[cr * 6 + e];
            else { int o = cr - 64; vv[e] = w1[o * 6 + 3 + e] - w1[o * 6 + e]; }
        }
        Ws[tid] = make_float4(vv[0], vv[1], vv[2], 0.f);
    }
    __syncthreads();

    unsigned long long acc2[4][4];
#pragma unroll
    for (int qi = 0; qi < 4; ++qi)
#pragma unroll
        for (int ci = 0; ci < 4; ++ci) acc2[qi][ci] = 0ull;
    U64x2 xv[4], wv[4];
#pragma unroll
    for (int qi = 0; qi < 4; ++qi) xv[qi] = asu64x2(Xs[ty + 16 * qi]);
#pragma unroll
    for (int ci = 0; ci < 4; ++ci) wv[ci] = asu64x2(Ws[tx + 16 * ci]);
#pragma unroll
    for (int qi = 0; qi < 4; ++qi)
#pragma unroll
        for (int ci = 0; ci < 4; ++ci) {
            fma2(acc2[qi][ci], xv[qi].a, wv[ci].a);
            fma2(acc2[qi][ci], xv[qi].b, wv[ci].b);
        }
#pragma unroll
    for (int qi = 0; qi < 4; ++qi)
#pragma unroll
        for (int ci = 0; ci < 4; ++ci)
            g_AC[(size_t)(rowbase + ty + 16 * qi) * 128 + colbase + tx + 16 * ci] =
                f2sum(acc2[qi][ci]);
}

// ---------------- weight prep ----------------
__global__ void prep_wc_kernel(const float* __restrict__ w, int O, int D, int DPAD) {
    int i = blockIdx.x * blockDim.x + threadIdx.x;
    int total = 2 * O * DPAD;
    if (i >= total) return;
    int r = i / DPAD, d = i % DPAD;
    float v = 0.f;
    if (d < D) {
        if (r < O) v = w[r * 2 * D + d];
        else { int o = r - O; v = w[o * 2 * D + D + d] - w[o * 2 * D + d]; }
    }
    g_wc[i] = v;
}

// ---------------- register-tiled GEMM (64x64), optional w5 epilogue -----
template<int DPAD, bool W5MAX>
__global__ void __launch_bounds__(256) gemm_kernel(
    int xoff, const float* __restrict__ wext, int ldw, int ldo,
    const float* __restrict__ gg, const float* __restrict__ bb)
{
    constexpr int DC  = (DPAD < 32) ? DPAD : 32;
    constexpr int RC  = DC / 4;
    constexpr int SWM = (RC >= 8) ? 7 : 0;
    constexpr int NCH = DPAD / DC;
    constexpr int TR4 = 64 * RC;
    constexpr int NL  = (TR4 + 255) / 256;
    __shared__ float4 Xs[2 * TR4];
    __shared__ float4 Ws[2 * TR4];
    const float* x = g_cat + xoff;
    const float* w = W5MAX ? wext : g_wc;
    int tid = threadIdx.x, tx = tid & 15, ty = tid >> 4;
    int rowbase = blockIdx.x * 64, colbase = blockIdx.y * 64;
    unsigned long long acc2[4][4];
#pragma unroll
    for (int qi = 0; qi < 4; ++qi)
#pragma unroll
        for (int ci = 0; ci < 4; ++ci) acc2[qi][ci] = 0ull;

    float4 xreg[NL], wreg[NL];
    auto load_xw = [&](int ch) {
        int d0 = ch * DC;
#pragma unroll
        for (int l = 0; l < NL; ++l) {
            int i = tid + l * 256;
            if ((TR4 % 256 == 0) || i < TR4) {
                int r = i / RC, dv = i % RC;
                xreg[l] = *(const float4*)(x + (size_t)(rowbase + r) * 512 + d0 + 4 * dv);
                wreg[l] = *(const float4*)(w + (size_t)(colbase + r) * ldw + d0 + 4 * dv);
            }
        }
    };
    auto store_xw = [&](int buf) {
#pragma unroll
        for (int l = 0; l < NL; ++l) {
            int i = tid + l * 256;
            if ((TR4 % 256 == 0) || i < TR4) {
                int r = i / RC, dv = i % RC;
                Xs[buf * TR4 + r * RC + (dv ^ (r & SWM))] = xreg[l];
                Ws[buf * TR4 + r * RC + (dv ^ (r & SWM))] = wreg[l];
            }
        }
    };

    load_xw(0);
    for (int ch = 0; ch < NCH; ++ch) {
        int buf = ch & 1;
        store_xw(buf);
        if (ch + 1 < NCH) load_xw(ch + 1);
        __syncthreads();
        const float4* Xb = Xs + buf * TR4;
        const float4* Wb = Ws + buf * TR4;
#pragma unroll
        for (int dv = 0; dv < RC; ++dv) {
            U64x2 xv[4], wv[4];
#pragma unroll
            for (int qi = 0; qi < 4; ++qi)
                xv[qi] = asu64x2(Xb[(ty + 16 * qi) * RC + (dv ^ (ty & SWM))]);
#pragma unroll
            for (int ci = 0; ci < 4; ++ci)
                wv[ci] = asu64x2(Wb[(tx + 16 * ci) * RC + (dv ^ (tx & SWM))]);
#pragma unroll
            for (int qi = 0; qi < 4; ++qi)
#pragma unroll
                for (int ci = 0; ci < 4; ++ci) {
                    fma2(acc2[qi][ci], xv[qi].a, wv[ci].a);
                    fma2(acc2[qi][ci], xv[qi].b, wv[ci].b);
                }
        }
        __syncthreads();
    }

    if constexpr (!W5MAX) {
#pragma unroll
        for (int qi = 0; qi < 4; ++qi)
#pragma unroll
            for (int ci = 0; ci < 4; ++ci)
                g_AC[(size_t)(rowbase + ty + 16 * qi) * ldo + colbase + tx + 16 * ci] =
                    f2sum(acc2[qi][ci]);
    } else {
        float cm[4];
#pragma unroll
        for (int ci = 0; ci < 4; ++ci) {
            int col = colbase + tx + 16 * ci;
            float g = BNS * gg[col], be = bb[col];
            float m = NEG_INF;
#pragma unroll
            for (int qi = 0; qi < 4; ++qi) {
                float v = g * f2sum(acc2[qi][ci]) + be;
                v = (v > 0.f) ? v : SLOPE * v;
                m = fmaxf(m, v);
            }
            cm[ci] = m;
        }
        float* R = (float*)Xs;
#pragma unroll
        for (int ci = 0; ci < 4; ++ci) R[ty * 64 + tx + 16 * ci] = cm[ci];
        __syncthreads();
        if (tid < 64) {
            float m = R[tid];
#pragma unroll
            for (int t = 1; t < 16; ++t) m = fmaxf(m, R[t * 64 + tid]);
            g_part[(size_t)blockIdx.x * 1024 + colbase + tid] = m;
        }
    }
}

// ---------------- gather + bn + lrelu + max, fused next-layer sqnorm -------
__global__ void edgemax_kernel(const float* __restrict__ gamma, const float* __restrict__ beta,
                               int O, int catoff) {
    int n = blockIdx.x;
    int o = threadIdx.x;
    int b = n >> 12;
    __shared__ int sidx[K];
    __shared__ float ps[8];
    if (o < K) sidx[o] = g_knn[(size_t)n * K + o];
    __syncthreads();
    int twoO = 2 * O;
    float cterm = g_AC[(size_t)n * twoO + O + o];
    float g = BNS * gamma[o], be = beta[o];
    int base = b << 12;
    float m = NEG_INF;
#pragma unroll
    for (int j = 0; j < K; ++j) {
        float a = g_AC[(size_t)(base + sidx[j]) * twoO + o];
        float v = g * (a + cterm) + be;
        v = (v > 0.f) ? v : SLOPE * v;
        m = fmaxf(m, v);
    }
    g_cat[(size_t)n * 512 + catoff + o] = m;

    float p = m * m;
#pragma unroll
    for (int off = 16; off; off >>= 1) p += __shfl_down_sync(0xffffffffu, p, off);
    if ((o & 31) == 0) ps[o >> 5] = p;
    __syncthreads();
    if (o == 0) {
        float s = 0.f;
        int nw = O >> 5;
        for (int w = 0; w < nw; ++w) s += ps[w];
        g_sq[n] = s;
    }
}

// ---------------- final max reduce + warp-per-output MLP head -------------
__global__ void maxreduce_kernel() {
    int i = blockIdx.x * blockDim.x + threadIdx.x;
    if (i >= B * 1024) return;
    int b = i / 1024, o = i % 1024;
    float m = NEG_INF;
    for (int j = 0; j < 64; ++j)
        m = fmaxf(m, g_part[(size_t)(b * 64 + j) * 1024 + o]);
    g_h0[i] = m;
}

__global__ void fc1_kernel(const float* __restrict__ fw1, const float* __restrict__ fg1,
                           const float* __restrict__ fbt1) {
    int gw = (blockIdx.x * blockDim.x + threadIdx.x) >> 5;
    int lane = threadIdx.x & 31;
    if (gw >= B * 512) return;
    int b = gw >> 9, o = gw & 511;
    const float* h = g_h0 + b * 1024;
    const float* wr = fw1 + (size_t)o * 1024;
    float s = 0.f;
    for (int c = lane; c < 1024; c += 32) s += h[c] * wr[c];
#pragma unroll
    for (int off = 16; off; off >>= 1) s += __shfl_down_sync(0xffffffffu, s, off);
    if (lane == 0) {
        float v = BNS * fg1[o] * s + fbt1[o];
        g_y1[gw] = (v > 0.f) ? v : SLOPE * v;
    }
}

__global__ void fc2_kernel(const float* __restrict__ fw2, const float* __restrict__ fb2,
                           const float* __restrict__ fg2, const float* __restrict__ fbt2) {
    int gw = (blockIdx.x * blockDim.x + threadIdx.x) >> 5;
    int lane = threadIdx.x & 31;
    if (gw >= B * 256) return;
    int b = gw >> 8, o = gw & 255;
    const float* h = g_y1 + b * 512;
    const float* wr = fw2 + (size_t)o * 512;
    float s = 0.f;
    for (int c = lane; c < 512; c += 32) s += h[c] * wr[c];
#pragma unroll
    for (int off = 16; off; off >>= 1) s += __shfl_down_sync(0xffffffffu, s, off);
    if (lane == 0) {
        float v = BNS * fg2[o] * (s + fb2[o]) + fbt2[o];
        g_y2[gw] = (v > 0.f) ? v : SLOPE * v;
    }
}

__global__ void fc3_kernel(const float* __restrict__ fw3, const float* __restrict__ fb3,
                           float* __restrict__ out) {
    int gw = threadIdx.x >> 5;
    int lane = threadIdx.x & 31;
    if (gw >= B * 3) return;
    int b = gw / 3, o = gw % 3;
    const float* h = g_y2 + b * 256;
    const float* wr = fw3 + (size_t)o * 256;
    float s = 0.f;
    for (int c = lane; c < 256; c += 32) s += h[c] * wr[c];
#pragma unroll
    for (int off = 16; off; off >>= 1) s += __shfl_down_sync(0xffffffffu, s, off);
    if (lane == 0) out[gw] = s + fb3[o];
}

// ---------------- launch ----------------
static int knn_smem_bytes(int R4) {
    int pad = R4 + 1;
    int s = 64 * pad * 16 + 2 * 32 * pad * 16 + 64 * 33 * 4;
    int merge = 64 * 4 * K * 8;
    return s > merge ? s : merge;
}

extern "C" void kernel_launch(void* const* d_in, const int* in_sizes, int n_in,
                              void* d_out, int out_size) {
    const float* points = (const float*)d_in[0];
    const float* w1 = (const float*)d_in[2];
    const float* g1 = (const float*)d_in[3];
    const float* b1 = (const float*)d_in[4];
    const float* w2 = (const float*)d_in[5];
    const float* g2 = (const float*)d_in[6];
    const float* b2 = (const float*)d_in[7];
    const float* w3 = (const float*)d_in[8];
    const float* g3 = (const float*)d_in[9];
    const float* b3 = (const float*)d_in[10];
    const float* w4 = (const float*)d_in[11];
    const float* g4 = (const float*)d_in[12];
    const float* b4 = (const float*)d_in[13];
    const float* w5 = (const float*)d_in[14];
    const float* g5 = (const float*)d_in[15];
    const float* b5 = (const float*)d_in[16];
    const float* fw1 = (const float*)d_in[17];
    const float* fg1 = (const float*)d_in[18];
    const float* fbt1 = (const float*)d_in[19];
    const float* fw2 = (const float*)d_in[20];
    const float* fb2 = (const float*)d_in[21];
    const float* fg2 = (const float*)d_in[22];
    const float* fbt2 = (const float*)d_in[23];
    const float* fw3 = (const float*)d_in[24];
    const float* fb3 = (const float*)d_in[25];
    float* out = (float*)d_out;

    int sm1 = 64 * 16 + 2 * 32 * 16 + 64 * 33 * 4;
    int merge1 = 64 * 4 * K * 8;
    if (merge1 > sm1) sm1 = merge1;
    int sm16 = knn_smem_bytes(16);
    int sm32 = knn_smem_bytes(32);
    static bool attr_done = false;
    if (!attr_done) {
        cudaFuncSetAttribute(knn1_kernel,        cudaFuncAttributeMaxDynamicSharedMemorySize, sm1);
        cudaFuncSetAttribute(knn_kernel<64, 4>,  cudaFuncAttributeMaxDynamicSharedMemorySize, sm16);
        cudaFuncSetAttribute(knn_kernel<128, 3>, cudaFuncAttributeMaxDynamicSharedMemorySize, sm32);
        attr_done = true;
    }

    dim3 knngrid(N / 64, B, NSPLIT);
    int mergegrid = (BN + 255) / 256;

    // ---- EdgeConv 1 (D=3, O=64) -> cat cols [0,64)
    knn1_kernel<<<knngrid, 256, sm1>>>(points);               // idx 0
    knnmerge_kernel<<<mergegrid, 256>>>();                    // idx 1
    gemm1_kernel<<<dim3(BN / 64, 2), 256>>>(points, w1);      // idx 2
    edgemax_kernel<<<BN, 64>>>(g1, b1, 64, 0);                // idx 3

    // ---- EdgeConv 2 (D=64, O=64) -> cat cols [64,128)
    knn_kernel<64, 4><<<knngrid, 256, sm16>>>(0);             // idx 4
    knnmerge_kernel<<<mergegrid, 256>>>();
    prep_wc_kernel<<<(2 * 64 * 64 + 255) / 256, 256>>>(w2, 64, 64, 64);
    gemm_kernel<64, false><<<dim3(BN / 64, 2), 256>>>(0, nullptr, 64, 128, nullptr, nullptr);
    edgemax_kernel<<<BN, 64>>>(g2, b2, 64, 64);

    // ---- EdgeConv 3 (D=64, O=128) -> cat cols [128,256)
    knn_kernel<64, 4><<<knngrid, 256, sm16>>>(64);
    knnmerge_kernel<<<mergegrid, 256>>>();
    prep_wc_kernel<<<(2 * 128 * 64 + 255) / 256, 256>>>(w3, 128, 64, 64);
    gemm_kernel<64, false><<<dim3(BN / 64, 4), 256>>>(64, nullptr, 64, 256, nullptr, nullptr);
    edgemax_kernel<<<BN, 128>>>(g3, b3, 128, 128);

    // ---- EdgeConv 4 (D=128, O=256) -> cat cols [256,512)
    knn_kernel<128, 3><<<knngrid, 256, sm32>>>(128);
    knnmerge_kernel<<<mergegrid, 256>>>();
    prep_wc_kernel<<<(2 * 256 * 128 + 255) / 256, 256>>>(w4, 256, 128, 128);
    gemm_kernel<128, false><<<dim3(BN / 64, 8), 256>>>(128, nullptr, 128, 512, nullptr, nullptr);
    edgemax_kernel<<<BN, 256>>>(g4, b4, 256, 256);

    // ---- w5 GEMM + bn + lrelu + row-block max
    gemm_kernel<512, true><<<dim3(BN / 64, 16), 256>>>(0, w5, 512, 0, g5, b5);
    maxreduce_kernel<<<(B * 1024 + 255) / 256, 256>>>();

    // ---- MLP head
    fc1_kernel<<<(B * 512 * 32 + 255) / 256, 256>>>(fw1, fg1, fbt1);
    fc2_kernel<<<(B * 256 * 32 + 255) / 256, 256>>>(fw2, fb2, fg2, fbt2);
    fc3_kernel<<<1, 384>>>(fw3, fb3, out);
}